// round 16
// baseline (speedup 1.0000x reference)
#include <cuda_runtime.h>
#include <cuda_bf16.h>
#include <cstdint>
#include <math.h>

#define BATCH   4096
#define DIMN    256
#define FPC_    8
#define NBLK    (BATCH / FPC_)          // 512
#define PPB     28
#define NPAIRS  (NBLK * PPB)            // 14336
#define MT      128
#define NT      128
#define NJT     (BATCH / NT)            // 32 tile-blocks
#define NTILES  (NJT * (NJT + 1) / 2)   // 528 upper-tri tiles
#define KC      32                      // K chunk (bf16)
#define NKCH    (DIMN / KC)             // 8
#define PITCH   80                      // smem row pitch bytes (64 data + 16 pad)
#define TILEB   (MT * PITCH)            // 10240 bytes per tile
#define STAGEB  (3 * TILEB)             // 30720 bytes per stage (Ahi, Bhi, Blo)
#define SMTOT   (2 * STAGEB + (NT + MT) * 4 + MT * 2 * 4 + NT * 4 * 4)  // 65024
#define SHIFT   20.0f

// ---------------- device scratch (no allocs allowed) ----------------
__device__ __nv_bfloat16 g_hi[BATCH * DIMN];
__device__ __nv_bfloat16 g_lo[BATCH * DIMN];
__device__ float g_norm[BATCH];
__device__ float g_SpartT[BATCH * NJT];   // [row][slot] — coalesced pair gather
__device__ float g_pairsum[NBLK];
__device__ unsigned int g_count = 0;

__constant__ int c_pa[PPB] = {0,0,0,0,0,0,0,1,1,1,1,1,1,2,2,2,2,2,3,3,3,3,4,4,4,5,5,6};
__constant__ int c_pb[PPB] = {1,2,3,4,5,6,7,2,3,4,5,6,7,3,4,5,6,7,4,5,6,7,5,6,7,6,7,7};

// ---------------- helpers ----------------
__device__ __forceinline__ uint32_t smem_u32(const void* p) {
    uint32_t a;
    asm("{ .reg .u64 t; cvta.to.shared.u64 t, %1; cvt.u32.u64 %0, t; }" : "=r"(a) : "l"(p));
    return a;
}
__device__ __forceinline__ void ldsm4(uint32_t* r, uint32_t addr) {
    asm volatile("ldmatrix.sync.aligned.m8n8.x4.shared.b16 {%0,%1,%2,%3}, [%4];"
        : "=r"(r[0]), "=r"(r[1]), "=r"(r[2]), "=r"(r[3]) : "r"(addr));
}
__device__ __forceinline__ void mma_bf16(float* c, const uint32_t* a,
                                         uint32_t b0, uint32_t b1) {
    asm volatile("mma.sync.aligned.m16n8k16.row.col.f32.bf16.bf16.f32 "
        "{%0,%1,%2,%3}, {%4,%5,%6,%7}, {%8,%9}, {%0,%1,%2,%3};"
        : "+f"(c[0]), "+f"(c[1]), "+f"(c[2]), "+f"(c[3])
        : "r"(a[0]), "r"(a[1]), "r"(a[2]), "r"(a[3]), "r"(b0), "r"(b1));
}
__device__ __forceinline__ void cp16(uint32_t saddr, const void* gptr) {
    asm volatile("cp.async.cg.shared.global [%0], [%1], 16;"
        :: "r"(saddr), "l"(gptr));
}
#define CP_COMMIT() asm volatile("cp.async.commit_group;" ::: "memory")
#define CP_WAIT1()  asm volatile("cp.async.wait_group 1;" ::: "memory")
#define CP_WAIT0()  asm volatile("cp.async.wait_group 0;" ::: "memory")

// ---------------------------------------------------------------------------
// K1: fused hi/lo bf16 split + squared row norms. One warp per row.
// ---------------------------------------------------------------------------
__global__ void prep_kernel(const float* __restrict__ x) {
    const int warp = threadIdx.x >> 5, lane = threadIdx.x & 31;
    const int row  = blockIdx.x * 8 + warp;
    const float4* xr = (const float4*)(x + (size_t)row * DIMN);
    __nv_bfloat162* ph = (__nv_bfloat162*)(g_hi + (size_t)row * DIMN);
    __nv_bfloat162* pl = (__nv_bfloat162*)(g_lo + (size_t)row * DIMN);

    float s = 0.f;
    #pragma unroll
    for (int h = 0; h < 2; h++) {
        const int q = lane * 2 + h;
        float4 v = xr[q];
        s += v.x*v.x + v.y*v.y + v.z*v.z + v.w*v.w;
        __nv_bfloat16 h0 = __float2bfloat16(v.x), h1 = __float2bfloat16(v.y);
        __nv_bfloat16 h2 = __float2bfloat16(v.z), h3 = __float2bfloat16(v.w);
        __nv_bfloat16 l0 = __float2bfloat16(v.x - __bfloat162float(h0));
        __nv_bfloat16 l1 = __float2bfloat16(v.y - __bfloat162float(h1));
        __nv_bfloat16 l2 = __float2bfloat16(v.z - __bfloat162float(h2));
        __nv_bfloat16 l3 = __float2bfloat16(v.w - __bfloat162float(h3));
        ph[q*2]   = __nv_bfloat162(h0, h1);
        ph[q*2+1] = __nv_bfloat162(h2, h3);
        pl[q*2]   = __nv_bfloat162(l0, l1);
        pl[q*2+1] = __nv_bfloat162(l2, l3);
    }
    #pragma unroll
    for (int o = 16; o; o >>= 1) s += __shfl_down_sync(0xffffffffu, s, o);
    if (lane == 0) g_norm[row] = s;
}

// ---------------------------------------------------------------------------
// K2: symmetric Gram, upper-tri tiles, cp.async double-buffered.
//     2-product split: dot ~= hi.hi + hi.lo.  Writes g_SpartT transposed.
// ---------------------------------------------------------------------------
__global__ void __launch_bounds__(256, 2) gram_kernel() {
    extern __shared__ uint8_t dsm[];
    float* norms_c = (float*)(dsm + 2 * STAGEB);
    float* norms_r = norms_c + NT;
    float (*red_r)[2] = (float (*)[2])(norms_r + MT);
    float (*red_c)[4] = (float (*)[4])((float*)red_r + MT * 2);

    // decode linear tile id -> (I, J) with I <= J
    int k = blockIdx.x;
    int J = (int)((sqrtf(8.0f * (float)k + 1.0f) - 1.0f) * 0.5f);
    while ((J + 1) * (J + 2) / 2 <= k) J++;
    while (J * (J + 1) / 2 > k) J--;
    int I = k - J * (J + 1) / 2;

    const int tid  = threadIdx.x;
    const int wid  = tid >> 5, lane = tid & 31;
    const int wr   = wid >> 1;            // 0..3 row-warp
    const int wc   = wid & 1;             // 0..1 col-warp
    const int rowBase = I * MT;
    const int colBase = J * NT;
    const bool isDiag = (I == J);

    if (tid < 128) norms_c[tid] = g_norm[colBase + tid];
    else           norms_r[tid - 128] = g_norm[rowBase + tid - 128];

    const uint32_t st_u32[2] = { smem_u32(dsm), smem_u32(dsm) + STAGEB };

    float acc[2][8][4];
    #pragma unroll
    for (int mf = 0; mf < 2; mf++)
        #pragma unroll
        for (int nf = 0; nf < 8; nf++)
            #pragma unroll
            for (int e = 0; e < 4; e++) acc[mf][nf][e] = 0.f;

    const int r0 = tid >> 2;              // rows 0..63
    const int q0 = tid & 3;               // 16B quad

    // per-thread issue of one chunk into one stage (6/4 x 16B cp.async)
    auto issue = [&](int kc, int s) {
        const size_t gk = (size_t)kc * KC;
        const uint32_t sb = st_u32[s];
        #pragma unroll
        for (int half = 0; half < 2; half++) {
            const int r = r0 + half * 64;
            const uint32_t so = (uint32_t)(r * PITCH + q0 * 16);
            cp16(sb + so,              g_hi + (size_t)(rowBase + r) * DIMN + gk + q0 * 8);
            if (!isDiag)
                cp16(sb + TILEB + so,  g_hi + (size_t)(colBase + r) * DIMN + gk + q0 * 8);
            cp16(sb + 2 * TILEB + so,  g_lo + (size_t)(colBase + r) * DIMN + gk + q0 * 8);
        }
    };

    issue(0, 0); CP_COMMIT();
    issue(1, 1); CP_COMMIT();

    for (int kc = 0; kc < NKCH; kc++) {
        if (kc < NKCH - 1) { CP_WAIT1(); } else { CP_WAIT0(); }
        __syncthreads();                  // chunk kc's stage fully visible

        const uint32_t aHi = st_u32[kc & 1];
        const uint32_t bHi = isDiag ? aHi : (aHi + TILEB);
        const uint32_t bLo = aHi + 2 * TILEB;

        #pragma unroll
        for (int ks = 0; ks < 2; ks++) {
            const uint32_t koff = (uint32_t)(ks * 32 + (lane >> 4) * 16);
            uint32_t ahi[2][4], bh[4][4], bl[4][4];
            #pragma unroll
            for (int mf = 0; mf < 2; mf++) {
                uint32_t ro = (uint32_t)((wr * 32 + mf * 16 + (lane & 15)) * PITCH) + koff;
                ldsm4(ahi[mf], aHi + ro);
            }
            #pragma unroll
            for (int np = 0; np < 4; np++) {
                uint32_t co = (uint32_t)((wc * 64 + np * 16 + (lane & 15)) * PITCH) + koff;
                ldsm4(bh[np], bHi + co);
                ldsm4(bl[np], bLo + co);
            }
            #pragma unroll
            for (int mf = 0; mf < 2; mf++) {
                #pragma unroll
                for (int nf = 0; nf < 8; nf++) {
                    const int np = nf >> 1, w = nf & 1;
                    mma_bf16(acc[mf][nf], ahi[mf], bh[np][w], bh[np][w + 2]);
                    mma_bf16(acc[mf][nf], ahi[mf], bl[np][w], bl[np][w + 2]);
                }
            }
        }
        __syncthreads();                  // compute done before refilling this stage
        if (kc + 2 < NKCH) { issue(kc + 2, kc & 1); CP_COMMIT(); }
    }

    // ---- epilogue: d2 -> d -> exp; row sums + (off-diag) col sums ----
    float colsum[16];
    #pragma unroll
    for (int i = 0; i < 16; i++) colsum[i] = 0.f;

    #pragma unroll
    for (int mf = 0; mf < 2; mf++) {
        #pragma unroll
        for (int h = 0; h < 2; h++) {
            const int lr = wr * 32 + mf * 16 + (lane >> 2) + h * 8;
            const int gr = rowBase + lr;
            const float ni = norms_r[lr];
            const int rb = gr >> 3;
            float s = 0.f;
            #pragma unroll
            for (int nf = 0; nf < 8; nf++) {
                const int lc = wc * 64 + nf * 8 + (lane & 3) * 2;
                #pragma unroll
                for (int e = 0; e < 2; e++) {
                    float dot = acc[mf][nf][h * 2 + e];
                    int gc = colBase + lc + e;
                    float d2 = ni + norms_c[lc + e] - 2.0f * dot;
                    float d  = sqrtf(fmaxf(d2, 0.0f));
                    float ex = __expf(d - SHIFT);
                    if (isDiag && ((gc >> 3) == rb)) ex = 0.f;
                    s += ex;
                    colsum[nf * 2 + e] += ex;
                }
            }
            s += __shfl_xor_sync(0xffffffffu, s, 1);
            s += __shfl_xor_sync(0xffffffffu, s, 2);
            if ((lane & 3) == 0) red_r[lr][wc] = s;
        }
    }

    if (!isDiag) {
        #pragma unroll
        for (int i = 0; i < 16; i++) {
            colsum[i] += __shfl_xor_sync(0xffffffffu, colsum[i], 4);
            colsum[i] += __shfl_xor_sync(0xffffffffu, colsum[i], 8);
            colsum[i] += __shfl_xor_sync(0xffffffffu, colsum[i], 16);
        }
        if (lane < 4) {
            #pragma unroll
            for (int nf = 0; nf < 8; nf++)
                #pragma unroll
                for (int e = 0; e < 2; e++)
                    red_c[wc * 64 + nf * 8 + lane * 2 + e][wr] = colsum[nf * 2 + e];
        }
    }
    __syncthreads();

    if (tid < MT) {
        g_SpartT[(size_t)(rowBase + tid) * NJT + J] = red_r[tid][0] + red_r[tid][1];
        if (!isDiag)
            g_SpartT[(size_t)(colBase + tid) * NJT + I] =
                red_c[tid][0] + red_c[tid][1] + red_c[tid][2] + red_c[tid][3];
    }
}

// ---------------------------------------------------------------------------
// K3: fused LSE + pair losses + final mean (threadfence reduction).
//     LSE gather is now coalesced: one warp reads row's 32 contiguous slots.
// ---------------------------------------------------------------------------
__global__ void __launch_bounds__(256) pair_kernel(const float* __restrict__ x,
                                                   float* __restrict__ out) {
    __shared__ float xs[FPC_ * DIMN];
    __shared__ float lse_sh[FPC_];
    __shared__ float pl[PPB];
    __shared__ bool  amLast;
    __shared__ float wsum[8];
    const int blk = blockIdx.x, tid = threadIdx.x;
    const int warp = tid >> 5, lane = tid & 31;

    // fused LSE: warp w reduces the 32 contiguous slots of row blk*8+w
    {
        const int row = blk * FPC_ + warp;
        float s = g_SpartT[(size_t)row * NJT + lane];
        #pragma unroll
        for (int o = 16; o; o >>= 1) s += __shfl_down_sync(0xffffffffu, s, o);
        if (lane == 0) lse_sh[warp] = logf(s) + SHIFT;
    }

    const float4* src = (const float4*)(x + (size_t)blk * FPC_ * DIMN);
    float4* dst = (float4*)xs;
    dst[tid] = src[tid]; dst[tid + 256] = src[tid + 256];
    __syncthreads();

    for (int p = warp; p < PPB; p += 8) {
        const int a = c_pa[p], b = c_pb[p];
        const float4* xa = (const float4*)(xs + a * DIMN);
        const float4* xb = (const float4*)(xs + b * DIMN);
        float4 a0 = xa[lane], a1 = xa[lane + 32];
        float4 b0 = xb[lane], b1 = xb[lane + 32];
        float dot = a0.x*b0.x + a0.y*b0.y + a0.z*b0.z + a0.w*b0.w
                  + a1.x*b1.x + a1.y*b1.y + a1.z*b1.z + a1.w*b1.w;
        #pragma unroll
        for (int o = 16; o; o >>= 1) dot += __shfl_down_sync(0xffffffffu, dot, o);
        if (lane == 0) {
            int ga = blk * FPC_ + a, gb = blk * FPC_ + b;
            float d2 = g_norm[ga] + g_norm[gb] - 2.0f * dot;
            float d  = sqrtf(fmaxf(d2, 0.0f));
            float z  = lse_sh[a] - d;
            pl[p] = (z > 20.0f) ? z : log1pf(expf(z));
        }
    }
    __syncthreads();
    if (tid == 0) {
        float s = 0.f;
        #pragma unroll
        for (int p = 0; p < PPB; p++) s += pl[p];
        g_pairsum[blk] = s;
        __threadfence();
        unsigned prev = atomicAdd(&g_count, 1u);
        amLast = (prev == NBLK - 1);
    }
    __syncthreads();

    if (amLast) {
        __threadfence();
        float v = g_pairsum[tid] + g_pairsum[tid + 256];
        #pragma unroll
        for (int o = 16; o; o >>= 1) v += __shfl_down_sync(0xffffffffu, v, o);
        if (lane == 0) wsum[warp] = v;
        __syncthreads();
        if (tid == 0) {
            float t = 0.f;
            #pragma unroll
            for (int i = 0; i < 8; i++) t += wsum[i];
            out[0] = t / (float)NPAIRS;
            g_count = 0;                 // reset for graph replay
        }
    }
}

// ---------------------------------------------------------------------------
extern "C" void kernel_launch(void* const* d_in, const int* in_sizes, int n_in,
                              void* d_out, int out_size) {
    const float* x = (const float*)d_in[0];
    float* out = (float*)d_out;

    cudaFuncSetAttribute(gram_kernel,
                         cudaFuncAttributeMaxDynamicSharedMemorySize, SMTOT);

    prep_kernel<<<BATCH / 8, 256>>>(x);
    gram_kernel<<<NTILES, 256, SMTOT>>>();
    pair_kernel<<<NBLK, 256>>>(x, out);
}

// round 17
// speedup vs baseline: 1.3184x; 1.3184x over previous
#include <cuda_runtime.h>
#include <cuda_bf16.h>
#include <cstdint>
#include <math.h>

#define BATCH   4096
#define DIMN    256
#define FPC_    8
#define NBLK    (BATCH / FPC_)          // 512
#define PPB     28
#define NPAIRS  (NBLK * PPB)            // 14336
#define MT      128
#define NT      128
#define NJT     (BATCH / NT)            // 32 tile-blocks
#define NTILES  (NJT * (NJT + 1) / 2)   // 528 upper-tri tiles
#define KC      32                      // K chunk (bf16)
#define NKCH    (DIMN / KC)             // 8
#define PITCH   80                      // smem row pitch bytes (64 data + 16 pad)
#define TILEB   (MT * PITCH)            // 10240 bytes per tile
#define STAGEB  (2 * TILEB)             // 20480 bytes per stage (Ahi, Bhi)
#define SMTOT   (2 * STAGEB + (NT + MT) * 4 + MT * 2 * 4 + NT * 4 * 4)  // 45056
#define SHIFT   20.0f

// ---------------- device scratch (no allocs allowed) ----------------
__device__ __nv_bfloat16 g_hi[BATCH * DIMN];
__device__ float g_norm[BATCH];
__device__ float g_SpartT[BATCH * NJT];   // [row][slot]
__device__ float g_pairsum[NBLK];
__device__ unsigned int g_count = 0;

__constant__ int c_pa[PPB] = {0,0,0,0,0,0,0,1,1,1,1,1,1,2,2,2,2,2,3,3,3,3,4,4,4,5,5,6};
__constant__ int c_pb[PPB] = {1,2,3,4,5,6,7,2,3,4,5,6,7,3,4,5,6,7,4,5,6,7,5,6,7,6,7,7};

// ---------------- helpers ----------------
__device__ __forceinline__ uint32_t smem_u32(const void* p) {
    uint32_t a;
    asm("{ .reg .u64 t; cvta.to.shared.u64 t, %1; cvt.u32.u64 %0, t; }" : "=r"(a) : "l"(p));
    return a;
}
__device__ __forceinline__ void ldsm4(uint32_t* r, uint32_t addr) {
    asm volatile("ldmatrix.sync.aligned.m8n8.x4.shared.b16 {%0,%1,%2,%3}, [%4];"
        : "=r"(r[0]), "=r"(r[1]), "=r"(r[2]), "=r"(r[3]) : "r"(addr));
}
__device__ __forceinline__ void mma_bf16(float* c, const uint32_t* a,
                                         uint32_t b0, uint32_t b1) {
    asm volatile("mma.sync.aligned.m16n8k16.row.col.f32.bf16.bf16.f32 "
        "{%0,%1,%2,%3}, {%4,%5,%6,%7}, {%8,%9}, {%0,%1,%2,%3};"
        : "+f"(c[0]), "+f"(c[1]), "+f"(c[2]), "+f"(c[3])
        : "r"(a[0]), "r"(a[1]), "r"(a[2]), "r"(a[3]), "r"(b0), "r"(b1));
}
__device__ __forceinline__ void cp16(uint32_t saddr, const void* gptr) {
    asm volatile("cp.async.cg.shared.global [%0], [%1], 16;"
        :: "r"(saddr), "l"(gptr));
}
#define CP_COMMIT() asm volatile("cp.async.commit_group;" ::: "memory")
#define CP_WAIT1()  asm volatile("cp.async.wait_group 1;" ::: "memory")
#define CP_WAIT0()  asm volatile("cp.async.wait_group 0;" ::: "memory")

// ---------------------------------------------------------------------------
// K1: bf16 hi conversion + squared row norms. One warp per row.
// ---------------------------------------------------------------------------
__global__ void prep_kernel(const float* __restrict__ x) {
    const int warp = threadIdx.x >> 5, lane = threadIdx.x & 31;
    const int row  = blockIdx.x * 8 + warp;
    const float4* xr = (const float4*)(x + (size_t)row * DIMN);
    __nv_bfloat162* ph = (__nv_bfloat162*)(g_hi + (size_t)row * DIMN);

    float s = 0.f;
    #pragma unroll
    for (int h = 0; h < 2; h++) {
        const int q = lane * 2 + h;
        float4 v = xr[q];
        s += v.x*v.x + v.y*v.y + v.z*v.z + v.w*v.w;
        ph[q*2]   = __nv_bfloat162(__float2bfloat16(v.x), __float2bfloat16(v.y));
        ph[q*2+1] = __nv_bfloat162(__float2bfloat16(v.z), __float2bfloat16(v.w));
    }
    #pragma unroll
    for (int o = 16; o; o >>= 1) s += __shfl_down_sync(0xffffffffu, s, o);
    if (lane == 0) g_norm[row] = s;
}

// ---------------------------------------------------------------------------
// K2: symmetric Gram, upper-tri tiles, cp.async double-buffered.
//     1-product: dot ~= hi.hi  (cross terms dropped; positives exact in K3)
// ---------------------------------------------------------------------------
__global__ void __launch_bounds__(256, 2) gram_kernel() {
    extern __shared__ uint8_t dsm[];
    float* norms_c = (float*)(dsm + 2 * STAGEB);
    float* norms_r = norms_c + NT;
    float (*red_r)[2] = (float (*)[2])(norms_r + MT);
    float (*red_c)[4] = (float (*)[4])((float*)red_r + MT * 2);

    // decode linear tile id -> (I, J) with I <= J
    int k = blockIdx.x;
    int J = (int)((sqrtf(8.0f * (float)k + 1.0f) - 1.0f) * 0.5f);
    while ((J + 1) * (J + 2) / 2 <= k) J++;
    while (J * (J + 1) / 2 > k) J--;
    int I = k - J * (J + 1) / 2;

    const int tid  = threadIdx.x;
    const int wid  = tid >> 5, lane = tid & 31;
    const int wr   = wid >> 1;            // 0..3 row-warp
    const int wc   = wid & 1;             // 0..1 col-warp
    const int rowBase = I * MT;
    const int colBase = J * NT;
    const bool isDiag = (I == J);

    if (tid < 128) norms_c[tid] = g_norm[colBase + tid];
    else           norms_r[tid - 128] = g_norm[rowBase + tid - 128];

    const uint32_t st_u32[2] = { smem_u32(dsm), smem_u32(dsm) + STAGEB };

    float acc[2][8][4];
    #pragma unroll
    for (int mf = 0; mf < 2; mf++)
        #pragma unroll
        for (int nf = 0; nf < 8; nf++)
            #pragma unroll
            for (int e = 0; e < 4; e++) acc[mf][nf][e] = 0.f;

    const int r0 = tid >> 2;              // rows 0..63
    const int q0 = tid & 3;               // 16B quad

    // per-thread issue of one chunk into one stage (4/2 x 16B cp.async)
    auto issue = [&](int kc, int s) {
        const size_t gk = (size_t)kc * KC;
        const uint32_t sb = st_u32[s];
        #pragma unroll
        for (int half = 0; half < 2; half++) {
            const int r = r0 + half * 64;
            const uint32_t so = (uint32_t)(r * PITCH + q0 * 16);
            cp16(sb + so,              g_hi + (size_t)(rowBase + r) * DIMN + gk + q0 * 8);
            if (!isDiag)
                cp16(sb + TILEB + so,  g_hi + (size_t)(colBase + r) * DIMN + gk + q0 * 8);
        }
    };

    issue(0, 0); CP_COMMIT();
    issue(1, 1); CP_COMMIT();

    for (int kc = 0; kc < NKCH; kc++) {
        if (kc < NKCH - 1) { CP_WAIT1(); } else { CP_WAIT0(); }
        __syncthreads();                  // chunk kc's stage fully visible

        const uint32_t aHi = st_u32[kc & 1];
        const uint32_t bHi = isDiag ? aHi : (aHi + TILEB);

        #pragma unroll
        for (int ks = 0; ks < 2; ks++) {
            const uint32_t koff = (uint32_t)(ks * 32 + (lane >> 4) * 16);
            uint32_t ahi[2][4], bh[4][4];
            #pragma unroll
            for (int mf = 0; mf < 2; mf++) {
                uint32_t ro = (uint32_t)((wr * 32 + mf * 16 + (lane & 15)) * PITCH) + koff;
                ldsm4(ahi[mf], aHi + ro);
            }
            #pragma unroll
            for (int np = 0; np < 4; np++) {
                uint32_t co = (uint32_t)((wc * 64 + np * 16 + (lane & 15)) * PITCH) + koff;
                ldsm4(bh[np], bHi + co);
            }
            #pragma unroll
            for (int mf = 0; mf < 2; mf++) {
                #pragma unroll
                for (int nf = 0; nf < 8; nf++) {
                    const int np = nf >> 1, w = nf & 1;
                    mma_bf16(acc[mf][nf], ahi[mf], bh[np][w], bh[np][w + 2]);
                }
            }
        }
        __syncthreads();                  // compute done before refilling this stage
        if (kc + 2 < NKCH) { issue(kc + 2, kc & 1); CP_COMMIT(); }
    }

    // ---- epilogue: d2 -> d -> exp; row sums + (off-diag) col sums ----
    float colsum[16];
    #pragma unroll
    for (int i = 0; i < 16; i++) colsum[i] = 0.f;

    #pragma unroll
    for (int mf = 0; mf < 2; mf++) {
        #pragma unroll
        for (int h = 0; h < 2; h++) {
            const int lr = wr * 32 + mf * 16 + (lane >> 2) + h * 8;
            const int gr = rowBase + lr;
            const float ni = norms_r[lr];
            const int rb = gr >> 3;
            float s = 0.f;
            #pragma unroll
            for (int nf = 0; nf < 8; nf++) {
                const int lc = wc * 64 + nf * 8 + (lane & 3) * 2;
                #pragma unroll
                for (int e = 0; e < 2; e++) {
                    float dot = acc[mf][nf][h * 2 + e];
                    int gc = colBase + lc + e;
                    float d2 = ni + norms_c[lc + e] - 2.0f * dot;
                    float d  = sqrtf(fmaxf(d2, 0.0f));
                    float ex = __expf(d - SHIFT);
                    if (isDiag && ((gc >> 3) == rb)) ex = 0.f;
                    s += ex;
                    colsum[nf * 2 + e] += ex;
                }
            }
            s += __shfl_xor_sync(0xffffffffu, s, 1);
            s += __shfl_xor_sync(0xffffffffu, s, 2);
            if ((lane & 3) == 0) red_r[lr][wc] = s;
        }
    }

    if (!isDiag) {
        #pragma unroll
        for (int i = 0; i < 16; i++) {
            colsum[i] += __shfl_xor_sync(0xffffffffu, colsum[i], 4);
            colsum[i] += __shfl_xor_sync(0xffffffffu, colsum[i], 8);
            colsum[i] += __shfl_xor_sync(0xffffffffu, colsum[i], 16);
        }
        if (lane < 4) {
            #pragma unroll
            for (int nf = 0; nf < 8; nf++)
                #pragma unroll
                for (int e = 0; e < 2; e++)
                    red_c[wc * 64 + nf * 8 + lane * 2 + e][wr] = colsum[nf * 2 + e];
        }
    }
    __syncthreads();

    if (tid < MT) {
        g_SpartT[(size_t)(rowBase + tid) * NJT + J] = red_r[tid][0] + red_r[tid][1];
        if (!isDiag)
            g_SpartT[(size_t)(colBase + tid) * NJT + I] =
                red_c[tid][0] + red_c[tid][1] + red_c[tid][2] + red_c[tid][3];
    }
}

// ---------------------------------------------------------------------------
// K3: fused LSE + pair losses + final mean (threadfence reduction).
//     Positives computed with exact fp32 dots from x.
// ---------------------------------------------------------------------------
__global__ void __launch_bounds__(256) pair_kernel(const float* __restrict__ x,
                                                   float* __restrict__ out) {
    __shared__ float xs[FPC_ * DIMN];
    __shared__ float lse_sh[FPC_];
    __shared__ float pl[PPB];
    __shared__ bool  amLast;
    __shared__ float wsum[8];
    const int blk = blockIdx.x, tid = threadIdx.x;
    const int warp = tid >> 5, lane = tid & 31;

    // fused LSE: warp w reduces the 32 contiguous slots of row blk*8+w
    {
        const int row = blk * FPC_ + warp;
        float s = g_SpartT[(size_t)row * NJT + lane];
        #pragma unroll
        for (int o = 16; o; o >>= 1) s += __shfl_down_sync(0xffffffffu, s, o);
        if (lane == 0) lse_sh[warp] = logf(s) + SHIFT;
    }

    const float4* src = (const float4*)(x + (size_t)blk * FPC_ * DIMN);
    float4* dst = (float4*)xs;
    dst[tid] = src[tid]; dst[tid + 256] = src[tid + 256];
    __syncthreads();

    for (int p = warp; p < PPB; p += 8) {
        const int a = c_pa[p], b = c_pb[p];
        const float4* xa = (const float4*)(xs + a * DIMN);
        const float4* xb = (const float4*)(xs + b * DIMN);
        float4 a0 = xa[lane], a1 = xa[lane + 32];
        float4 b0 = xb[lane], b1 = xb[lane + 32];
        float dot = a0.x*b0.x + a0.y*b0.y + a0.z*b0.z + a0.w*b0.w
                  + a1.x*b1.x + a1.y*b1.y + a1.z*b1.z + a1.w*b1.w;
        #pragma unroll
        for (int o = 16; o; o >>= 1) dot += __shfl_down_sync(0xffffffffu, dot, o);
        if (lane == 0) {
            int ga = blk * FPC_ + a, gb = blk * FPC_ + b;
            float d2 = g_norm[ga] + g_norm[gb] - 2.0f * dot;
            float d  = sqrtf(fmaxf(d2, 0.0f));
            float z  = lse_sh[a] - d;
            pl[p] = (z > 20.0f) ? z : log1pf(expf(z));
        }
    }
    __syncthreads();
    if (tid == 0) {
        float s = 0.f;
        #pragma unroll
        for (int p = 0; p < PPB; p++) s += pl[p];
        g_pairsum[blk] = s;
        __threadfence();
        unsigned prev = atomicAdd(&g_count, 1u);
        amLast = (prev == NBLK - 1);
    }
    __syncthreads();

    if (amLast) {
        __threadfence();
        float v = g_pairsum[tid] + g_pairsum[tid + 256];
        #pragma unroll
        for (int o = 16; o; o >>= 1) v += __shfl_down_sync(0xffffffffu, v, o);
        if (lane == 0) wsum[warp] = v;
        __syncthreads();
        if (tid == 0) {
            float t = 0.f;
            #pragma unroll
            for (int i = 0; i < 8; i++) t += wsum[i];
            out[0] = t / (float)NPAIRS;
            g_count = 0;                 // reset for graph replay
        }
    }
}

// ---------------------------------------------------------------------------
extern "C" void kernel_launch(void* const* d_in, const int* in_sizes, int n_in,
                              void* d_out, int out_size) {
    const float* x = (const float*)d_in[0];
    float* out = (float*)d_out;

    cudaFuncSetAttribute(gram_kernel,
                         cudaFuncAttributeMaxDynamicSharedMemorySize, SMTOT);

    prep_kernel<<<BATCH / 8, 256>>>(x);
    gram_kernel<<<NTILES, 256, SMTOT>>>();
    pair_kernel<<<NBLK, 256>>>(x, out);
}